// round 3
// baseline (speedup 1.0000x reference)
#include <cuda_runtime.h>
#include <math.h>

#define Bsz  4
#define Sseq 2048
#define Dmod 1024
#define Hh   16
#define DHd  64
#define DFFd 4096
#define NROWS (Bsz*Sseq)        // 8192
#define AT_PAD 68
#define ATT_SMEM (4*64*AT_PAD*4)  // 69632 bytes

// -------- scratch (device globals: allocation-free) --------
__device__ float g_h  [(size_t)NROWS*Dmod];
__device__ float g_q  [(size_t)NROWS*Dmod];
__device__ float g_k  [(size_t)NROWS*Dmod];
__device__ float g_v  [(size_t)NROWS*Dmod];
__device__ float g_ctx[(size_t)NROWS*Dmod];
__device__ float g_x1 [(size_t)NROWS*Dmod];
__device__ float g_h2 [(size_t)NROWS*Dmod];
__device__ float g_ff [(size_t)NROWS*DFFd];

// ---------------- LayerNorm (quirk: (norm + shift) * scale, biased var, eps=1e-7)
__global__ void __launch_bounds__(256) ln_kernel(
    const float* __restrict__ x, const float* __restrict__ scale,
    const float* __restrict__ shift, float* __restrict__ y)
{
    int row = blockIdx.x;
    int tid = threadIdx.x;
    const float* xr = x + (size_t)row * Dmod;
    float4 v = *(const float4*)(xr + tid * 4);

    __shared__ float red[8];
    __shared__ float smean, srstd;

    float s = v.x + v.y + v.z + v.w;
    #pragma unroll
    for (int o = 16; o > 0; o >>= 1) s += __shfl_down_sync(0xffffffffu, s, o);
    if ((tid & 31) == 0) red[tid >> 5] = s;
    __syncthreads();
    if (tid == 0) {
        float t = 0.f;
        #pragma unroll
        for (int i = 0; i < 8; i++) t += red[i];
        smean = t * (1.0f / Dmod);
    }
    __syncthreads();
    float mean = smean;
    float d0 = v.x - mean, d1 = v.y - mean, d2 = v.z - mean, d3 = v.w - mean;
    float sq = d0*d0 + d1*d1 + d2*d2 + d3*d3;
    #pragma unroll
    for (int o = 16; o > 0; o >>= 1) sq += __shfl_down_sync(0xffffffffu, sq, o);
    if ((tid & 31) == 0) red[tid >> 5] = sq;
    __syncthreads();
    if (tid == 0) {
        float t = 0.f;
        #pragma unroll
        for (int i = 0; i < 8; i++) t += red[i];
        srstd = rsqrtf(t * (1.0f / Dmod) + 1e-7f);
    }
    __syncthreads();
    float r = srstd;
    float4 sc = *(const float4*)(scale + tid * 4);
    float4 sh = *(const float4*)(shift + tid * 4);
    float4 o;
    o.x = (d0 * r + sh.x) * sc.x;
    o.y = (d1 * r + sh.y) * sc.y;
    o.z = (d2 * r + sh.z) * sc.z;
    o.w = (d3 * r + sh.w) * sc.w;
    *(float4*)(y + (size_t)row * Dmod + tid * 4) = o;
}

// ---------------- GELU (tanh form, matching reference)
__device__ __forceinline__ float gelu_f(float x) {
    float x3 = x * x * x;
    return 0.5f * x * (1.0f + tanhf(0.79788456080286535588f * (x + 0.044715f * x3)));
}

// ---------------- SGEMM: C[m][n] = sum_k A[m][k] * Bw[n][k]   (A: MxK, Bw: NxK)
// EPI 1: scatter to [B,H,S,DH] (QKV)
// EPI 2/4: + bias[n] + res[m*N+n]   (Wo residual / FF2 residual)
// EPI 3: gelu(acc + bias[n])        (FF1)
template<int EPI>
__global__ void __launch_bounds__(256) gemm_kernel(
    const float* __restrict__ A, const float* __restrict__ Bw,
    const float* __restrict__ bias, const float* __restrict__ res,
    float* __restrict__ C, int M, int N, int K)
{
    __shared__ float As[8][128];
    __shared__ float Bs[8][128];
    int tid = threadIdx.x;
    int tx = tid & 15, ty = tid >> 4;
    int m0 = blockIdx.y * 128, n0 = blockIdx.x * 128;
    int lr = tid >> 1;          // 0..127
    int lk = (tid & 1) * 4;     // 0 or 4
    const float* Ap = A  + (size_t)(m0 + lr) * K + lk;
    const float* Bp = Bw + (size_t)(n0 + lr) * K + lk;

    float acc[8][8];
    #pragma unroll
    for (int i = 0; i < 8; i++)
        #pragma unroll
        for (int j = 0; j < 8; j++) acc[i][j] = 0.f;

    for (int k0 = 0; k0 < K; k0 += 8) {
        float4 av = *(const float4*)(Ap + k0);
        float4 bv = *(const float4*)(Bp + k0);
        __syncthreads();
        As[lk + 0][lr] = av.x; As[lk + 1][lr] = av.y;
        As[lk + 2][lr] = av.z; As[lk + 3][lr] = av.w;
        Bs[lk + 0][lr] = bv.x; Bs[lk + 1][lr] = bv.y;
        Bs[lk + 2][lr] = bv.z; Bs[lk + 3][lr] = bv.w;
        __syncthreads();
        #pragma unroll
        for (int kk = 0; kk < 8; kk++) {
            float4 a0 = *(const float4*)&As[kk][ty * 4];
            float4 a1 = *(const float4*)&As[kk][64 + ty * 4];
            float4 b0 = *(const float4*)&Bs[kk][tx * 4];
            float4 b1 = *(const float4*)&Bs[kk][64 + tx * 4];
            float a[8] = {a0.x, a0.y, a0.z, a0.w, a1.x, a1.y, a1.z, a1.w};
            float b[8] = {b0.x, b0.y, b0.z, b0.w, b1.x, b1.y, b1.z, b1.w};
            #pragma unroll
            for (int i = 0; i < 8; i++)
                #pragma unroll
                for (int j = 0; j < 8; j++) acc[i][j] += a[i] * b[j];
        }
    }

    #pragma unroll
    for (int i = 0; i < 8; i++) {
        int mo = m0 + ((i < 4) ? (ty * 4 + i) : (64 + ty * 4 + i - 4));
        #pragma unroll
        for (int j = 0; j < 8; j++) {
            int no = n0 + ((j < 4) ? (tx * 4 + j) : (64 + tx * 4 + j - 4));
            float v = acc[i][j];
            if (EPI == 1) {
                int b  = mo >> 11, s2 = mo & 2047;
                int hh = no >> 6,  dh = no & 63;
                C[(((size_t)(b * Hh + hh) * Sseq + s2) << 6) + dh] = v;
            } else if (EPI == 2 || EPI == 4) {
                size_t idx = (size_t)mo * N + no;
                C[idx] = v + bias[no] + res[idx];
            } else if (EPI == 3) {
                C[(size_t)mo * N + no] = gelu_f(v + bias[no]);
            } else {
                C[(size_t)mo * N + no] = v;
            }
        }
    }
}

// ---------------- Flash attention (causal), 64-query tiles, DH=64
// Q,K,V: [B,H,S,DH]; O written as [B,S,D] (heads re-interleaved)
__global__ void __launch_bounds__(256) attn_kernel(
    const float* __restrict__ Q, const float* __restrict__ K,
    const float* __restrict__ V, float* __restrict__ O)
{
    extern __shared__ float sm[];
    float* Qs = sm;
    float* Ks = sm + 64 * AT_PAD;
    float* Vs = sm + 2 * 64 * AT_PAD;
    float* Ps = sm + 3 * 64 * AT_PAD;

    int tid = threadIdx.x;
    int qt = blockIdx.x, bh = blockIdx.y;
    int b = bh >> 4, h = bh & 15;

    const float* Qg = Q + ((size_t)bh * Sseq + qt * 64) * DHd;
    #pragma unroll
    for (int rep = 0; rep < 4; rep++) {
        int lin = rep * 1024 + tid * 4;
        int r = lin >> 6, c = lin & 63;
        float4 v = *(const float4*)(Qg + lin);
        *(float4*)&Qs[r * AT_PAD + c] = v;
    }

    int qr = tid >> 2, ql = tid & 3;
    int qglob = qt * 64 + qr;
    float acc[16];
    #pragma unroll
    for (int i = 0; i < 16; i++) acc[i] = 0.f;
    float m_i = -1e30f, l_i = 0.f;

    for (int kt = 0; kt <= qt; kt++) {
        __syncthreads();  // protect Ks/Vs/Ps from previous iteration readers
        const float* Kg = K + ((size_t)bh * Sseq + kt * 64) * DHd;
        const float* Vg = V + ((size_t)bh * Sseq + kt * 64) * DHd;
        #pragma unroll
        for (int rep = 0; rep < 4; rep++) {
            int lin = rep * 1024 + tid * 4;
            int r = lin >> 6, c = lin & 63;
            *(float4*)&Ks[r * AT_PAD + c] = *(const float4*)(Kg + lin);
            *(float4*)&Vs[r * AT_PAD + c] = *(const float4*)(Vg + lin);
        }
        __syncthreads();

        // scores: thread handles kc = ql + 4j for j in 0..15
        float s[16];
        #pragma unroll
        for (int j = 0; j < 16; j++) s[j] = 0.f;
        #pragma unroll
        for (int d4 = 0; d4 < 16; d4++) {
            float4 q4 = *(const float4*)&Qs[qr * AT_PAD + d4 * 4];
            #pragma unroll
            for (int j = 0; j < 16; j++) {
                int kc = ql + j * 4;
                float4 k4 = *(const float4*)&Ks[kc * AT_PAD + d4 * 4];
                s[j] += q4.x * k4.x + q4.y * k4.y + q4.z * k4.z + q4.w * k4.w;
            }
        }
        float mrow = -1e30f;
        #pragma unroll
        for (int j = 0; j < 16; j++) {
            float sc = s[j] * 0.125f;   // 1/sqrt(64)
            int kglob = kt * 64 + ql + j * 4;
            if (kglob > qglob) sc = -1e30f;
            s[j] = sc;
            mrow = fmaxf(mrow, sc);
        }
        mrow = fmaxf(mrow, __shfl_xor_sync(0xffffffffu, mrow, 1));
        mrow = fmaxf(mrow, __shfl_xor_sync(0xffffffffu, mrow, 2));
        float m_new = fmaxf(m_i, mrow);
        float fac = __expf(m_i - m_new);
        float lrow = 0.f;
        #pragma unroll
        for (int j = 0; j < 16; j++) {
            float p = __expf(s[j] - m_new);
            lrow += p;
            Ps[qr * AT_PAD + ql + j * 4] = p;
        }
        lrow += __shfl_xor_sync(0xffffffffu, lrow, 1);
        lrow += __shfl_xor_sync(0xffffffffu, lrow, 2);
        l_i = l_i * fac + lrow;
        m_i = m_new;
        #pragma unroll
        for (int j = 0; j < 16; j++) acc[j] *= fac;
        __syncthreads();

        // PV: thread owns dh in [ql*16, ql*16+16)
        int dbase = ql * 16;
        #pragma unroll
        for (int kc4 = 0; kc4 < 16; kc4++) {
            float4 p4 = *(const float4*)&Ps[qr * AT_PAD + kc4 * 4];
            float parr[4] = {p4.x, p4.y, p4.z, p4.w};
            #pragma unroll
            for (int kk = 0; kk < 4; kk++) {
                float pp = parr[kk];
                const float* vrow = &Vs[(kc4 * 4 + kk) * AT_PAD + dbase];
                float4 v0 = *(const float4*)(vrow);
                float4 v1 = *(const float4*)(vrow + 4);
                float4 v2 = *(const float4*)(vrow + 8);
                float4 v3 = *(const float4*)(vrow + 12);
                acc[0]  += pp * v0.x; acc[1]  += pp * v0.y; acc[2]  += pp * v0.z; acc[3]  += pp * v0.w;
                acc[4]  += pp * v1.x; acc[5]  += pp * v1.y; acc[6]  += pp * v1.z; acc[7]  += pp * v1.w;
                acc[8]  += pp * v2.x; acc[9]  += pp * v2.y; acc[10] += pp * v2.z; acc[11] += pp * v2.w;
                acc[12] += pp * v3.x; acc[13] += pp * v3.y; acc[14] += pp * v3.z; acc[15] += pp * v3.w;
            }
        }
    }

    float inv = 1.0f / l_i;
    float* Og = O + (size_t)(b * Sseq + qglob) * Dmod + h * DHd + ql * 16;
    #pragma unroll
    for (int jj = 0; jj < 4; jj++) {
        float4 o;
        o.x = acc[jj * 4 + 0] * inv;
        o.y = acc[jj * 4 + 1] * inv;
        o.z = acc[jj * 4 + 2] * inv;
        o.w = acc[jj * 4 + 3] * inv;
        *(float4*)(Og + jj * 4) = o;
    }
}

// ---------------- launch
extern "C" void kernel_launch(void* const* d_in, const int* in_sizes, int n_in,
                              void* d_out, int out_size)
{
    const float* x    = (const float*)d_in[0];
    const float* Wq   = (const float*)d_in[1];
    const float* Wk   = (const float*)d_in[2];
    const float* Wv   = (const float*)d_in[3];
    const float* Wo   = (const float*)d_in[4];
    const float* bo   = (const float*)d_in[5];
    const float* W1   = (const float*)d_in[6];
    const float* b1   = (const float*)d_in[7];
    const float* W2   = (const float*)d_in[8];
    const float* b2   = (const float*)d_in[9];
    const float* ln1s = (const float*)d_in[10];
    const float* ln1b = (const float*)d_in[11];
    const float* ln2s = (const float*)d_in[12];
    const float* ln2b = (const float*)d_in[13];
    float* out = (float*)d_out;

    float *ph, *pq, *pk, *pv, *pctx, *px1, *ph2, *pff;
    cudaGetSymbolAddress((void**)&ph,   g_h);
    cudaGetSymbolAddress((void**)&pq,   g_q);
    cudaGetSymbolAddress((void**)&pk,   g_k);
    cudaGetSymbolAddress((void**)&pv,   g_v);
    cudaGetSymbolAddress((void**)&pctx, g_ctx);
    cudaGetSymbolAddress((void**)&px1,  g_x1);
    cudaGetSymbolAddress((void**)&ph2,  g_h2);
    cudaGetSymbolAddress((void**)&pff,  g_ff);

    cudaFuncSetAttribute(attn_kernel, cudaFuncAttributeMaxDynamicSharedMemorySize, ATT_SMEM);

    // 1) LN1
    ln_kernel<<<NROWS, 256>>>(x, ln1s, ln1b, ph);

    // 2) Q,K,V projections (scatter to [B,H,S,DH])
    dim3 gq(Dmod / 128, NROWS / 128);
    gemm_kernel<1><<<gq, 256>>>(ph, Wq, nullptr, nullptr, pq, NROWS, Dmod, Dmod);
    gemm_kernel<1><<<gq, 256>>>(ph, Wk, nullptr, nullptr, pk, NROWS, Dmod, Dmod);
    gemm_kernel<1><<<gq, 256>>>(ph, Wv, nullptr, nullptr, pv, NROWS, Dmod, Dmod);

    // 3) causal flash attention -> ctx in [B,S,D]
    attn_kernel<<<dim3(Sseq / 64, Bsz * Hh), 256, ATT_SMEM>>>(pq, pk, pv, pctx);

    // 4) Wo projection + bias + residual(x) -> x1
    gemm_kernel<2><<<gq, 256>>>(pctx, Wo, bo, x, px1, NROWS, Dmod, Dmod);

    // 5) LN2
    ln_kernel<<<NROWS, 256>>>(px1, ln2s, ln2b, ph2);

    // 6) FF1 + bias + GELU
    gemm_kernel<3><<<dim3(DFFd / 128, NROWS / 128), 256>>>(ph2, W1, b1, nullptr, pff, NROWS, DFFd, Dmod);

    // 7) FF2 + bias + residual(x1) -> out
    gemm_kernel<4><<<gq, 256>>>(pff, W2, b2, px1, out, NROWS, Dmod, DFFd);
}

// round 4
// speedup vs baseline: 1.0015x; 1.0015x over previous
#include <cuda_runtime.h>
#include <math.h>

#define Bsz  4
#define Sseq 2048
#define Dmod 1024
#define Hh   16
#define DHd  64
#define DFFd 4096
#define NROWS (Bsz*Sseq)        // 8192
#define AT_PAD 68
#define ATT_SMEM (4*64*AT_PAD*4)  // 69632 bytes

// -------- scratch (device globals: allocation-free) --------
__device__ float g_h  [(size_t)NROWS*Dmod];
__device__ float g_q  [(size_t)NROWS*Dmod];
__device__ float g_k  [(size_t)NROWS*Dmod];
__device__ float g_v  [(size_t)NROWS*Dmod];
__device__ float g_ctx[(size_t)NROWS*Dmod];
__device__ float g_x1 [(size_t)NROWS*Dmod];
__device__ float g_h2 [(size_t)NROWS*Dmod];
__device__ float g_ff [(size_t)NROWS*DFFd];

// ---------------- LayerNorm (quirk: (norm + shift) * scale, biased var, eps=1e-7)
__global__ void __launch_bounds__(256) ln_kernel(
    const float* __restrict__ x, const float* __restrict__ scale,
    const float* __restrict__ shift, float* __restrict__ y)
{
    int row = blockIdx.x;
    int tid = threadIdx.x;
    const float* xr = x + (size_t)row * Dmod;
    float4 v = *(const float4*)(xr + tid * 4);

    __shared__ float red[8];
    __shared__ float smean, srstd;

    float s = v.x + v.y + v.z + v.w;
    #pragma unroll
    for (int o = 16; o > 0; o >>= 1) s += __shfl_down_sync(0xffffffffu, s, o);
    if ((tid & 31) == 0) red[tid >> 5] = s;
    __syncthreads();
    if (tid == 0) {
        float t = 0.f;
        #pragma unroll
        for (int i = 0; i < 8; i++) t += red[i];
        smean = t * (1.0f / Dmod);
    }
    __syncthreads();
    float mean = smean;
    float d0 = v.x - mean, d1 = v.y - mean, d2 = v.z - mean, d3 = v.w - mean;
    float sq = d0*d0 + d1*d1 + d2*d2 + d3*d3;
    #pragma unroll
    for (int o = 16; o > 0; o >>= 1) sq += __shfl_down_sync(0xffffffffu, sq, o);
    if ((tid & 31) == 0) red[tid >> 5] = sq;
    __syncthreads();
    if (tid == 0) {
        float t = 0.f;
        #pragma unroll
        for (int i = 0; i < 8; i++) t += red[i];
        srstd = rsqrtf(t * (1.0f / Dmod) + 1e-7f);
    }
    __syncthreads();
    float r = srstd;
    float4 sc = *(const float4*)(scale + tid * 4);
    float4 sh = *(const float4*)(shift + tid * 4);
    float4 o;
    o.x = (d0 * r + sh.x) * sc.x;
    o.y = (d1 * r + sh.y) * sc.y;
    o.z = (d2 * r + sh.z) * sc.z;
    o.w = (d3 * r + sh.w) * sc.w;
    *(float4*)(y + (size_t)row * Dmod + tid * 4) = o;
}

// ---------------- GELU (tanh form, matching reference)
__device__ __forceinline__ float gelu_f(float x) {
    float x3 = x * x * x;
    return 0.5f * x * (1.0f + tanhf(0.79788456080286535588f * (x + 0.044715f * x3)));
}

// ---------------- SGEMM: C[m][n] = sum_k A[m][k] * Bw[n][k]   (A: MxK, Bw: NxK)
// EPI 1: scatter to [B,H,S,DH] (QKV)
// EPI 2/4: + bias[n] + res[m*N+n]   (Wo residual / FF2 residual)
// EPI 3: gelu(acc + bias[n])        (FF1)
template<int EPI>
__global__ void __launch_bounds__(256) gemm_kernel(
    const float* __restrict__ A, const float* __restrict__ Bw,
    const float* __restrict__ bias, const float* __restrict__ res,
    float* __restrict__ C, int M, int N, int K)
{
    __shared__ float As[8][128];
    __shared__ float Bs[8][128];
    int tid = threadIdx.x;
    int tx = tid & 15, ty = tid >> 4;
    int m0 = blockIdx.y * 128, n0 = blockIdx.x * 128;
    int lr = tid >> 1;          // 0..127
    int lk = (tid & 1) * 4;     // 0 or 4
    const float* Ap = A  + (size_t)(m0 + lr) * K + lk;
    const float* Bp = Bw + (size_t)(n0 + lr) * K + lk;

    float acc[8][8];
    #pragma unroll
    for (int i = 0; i < 8; i++)
        #pragma unroll
        for (int j = 0; j < 8; j++) acc[i][j] = 0.f;

    for (int k0 = 0; k0 < K; k0 += 8) {
        float4 av = *(const float4*)(Ap + k0);
        float4 bv = *(const float4*)(Bp + k0);
        __syncthreads();
        As[lk + 0][lr] = av.x; As[lk + 1][lr] = av.y;
        As[lk + 2][lr] = av.z; As[lk + 3][lr] = av.w;
        Bs[lk + 0][lr] = bv.x; Bs[lk + 1][lr] = bv.y;
        Bs[lk + 2][lr] = bv.z; Bs[lk + 3][lr] = bv.w;
        __syncthreads();
        #pragma unroll
        for (int kk = 0; kk < 8; kk++) {
            float4 a0 = *(const float4*)&As[kk][ty * 4];
            float4 a1 = *(const float4*)&As[kk][64 + ty * 4];
            float4 b0 = *(const float4*)&Bs[kk][tx * 4];
            float4 b1 = *(const float4*)&Bs[kk][64 + tx * 4];
            float a[8] = {a0.x, a0.y, a0.z, a0.w, a1.x, a1.y, a1.z, a1.w};
            float b[8] = {b0.x, b0.y, b0.z, b0.w, b1.x, b1.y, b1.z, b1.w};
            #pragma unroll
            for (int i = 0; i < 8; i++)
                #pragma unroll
                for (int j = 0; j < 8; j++) acc[i][j] += a[i] * b[j];
        }
    }

    #pragma unroll
    for (int i = 0; i < 8; i++) {
        int mo = m0 + ((i < 4) ? (ty * 4 + i) : (64 + ty * 4 + i - 4));
        #pragma unroll
        for (int j = 0; j < 8; j++) {
            int no = n0 + ((j < 4) ? (tx * 4 + j) : (64 + tx * 4 + j - 4));
            float v = acc[i][j];
            if (EPI == 1) {
                int b  = mo >> 11, s2 = mo & 2047;
                int hh = no >> 6,  dh = no & 63;
                C[(((size_t)(b * Hh + hh) * Sseq + s2) << 6) + dh] = v;
            } else if (EPI == 2 || EPI == 4) {
                size_t idx = (size_t)mo * N + no;
                C[idx] = v + bias[no] + res[idx];
            } else if (EPI == 3) {
                C[(size_t)mo * N + no] = gelu_f(v + bias[no]);
            } else {
                C[(size_t)mo * N + no] = v;
            }
        }
    }
}

// ---------------- Flash attention (causal), 64-query tiles, DH=64
// Q,K,V: [B,H,S,DH]; O written as [B,S,D] (heads re-interleaved)
__global__ void __launch_bounds__(256) attn_kernel(
    const float* __restrict__ Q, const float* __restrict__ K,
    const float* __restrict__ V, float* __restrict__ O)
{
    extern __shared__ float sm[];
    float* Qs = sm;
    float* Ks = sm + 64 * AT_PAD;
    float* Vs = sm + 2 * 64 * AT_PAD;
    float* Ps = sm + 3 * 64 * AT_PAD;

    int tid = threadIdx.x;
    int qt = blockIdx.x, bh = blockIdx.y;
    int b = bh >> 4, h = bh & 15;

    const float* Qg = Q + ((size_t)bh * Sseq + qt * 64) * DHd;
    #pragma unroll
    for (int rep = 0; rep < 4; rep++) {
        int lin = rep * 1024 + tid * 4;
        int r = lin >> 6, c = lin & 63;
        float4 v = *(const float4*)(Qg + lin);
        *(float4*)&Qs[r * AT_PAD + c] = v;
    }

    int qr = tid >> 2, ql = tid & 3;
    int qglob = qt * 64 + qr;
    float acc[16];
    #pragma unroll
    for (int i = 0; i < 16; i++) acc[i] = 0.f;
    float m_i = -1e30f, l_i = 0.f;

    for (int kt = 0; kt <= qt; kt++) {
        __syncthreads();  // protect Ks/Vs/Ps from previous iteration readers
        const float* Kg = K + ((size_t)bh * Sseq + kt * 64) * DHd;
        const float* Vg = V + ((size_t)bh * Sseq + kt * 64) * DHd;
        #pragma unroll
        for (int rep = 0; rep < 4; rep++) {
            int lin = rep * 1024 + tid * 4;
            int r = lin >> 6, c = lin & 63;
            *(float4*)&Ks[r * AT_PAD + c] = *(const float4*)(Kg + lin);
            *(float4*)&Vs[r * AT_PAD + c] = *(const float4*)(Vg + lin);
        }
        __syncthreads();

        // scores: thread handles kc = ql + 4j for j in 0..15
        float s[16];
        #pragma unroll
        for (int j = 0; j < 16; j++) s[j] = 0.f;
        #pragma unroll
        for (int d4 = 0; d4 < 16; d4++) {
            float4 q4 = *(const float4*)&Qs[qr * AT_PAD + d4 * 4];
            #pragma unroll
            for (int j = 0; j < 16; j++) {
                int kc = ql + j * 4;
                float4 k4 = *(const float4*)&Ks[kc * AT_PAD + d4 * 4];
                s[j] += q4.x * k4.x + q4.y * k4.y + q4.z * k4.z + q4.w * k4.w;
            }
        }
        float mrow = -1e30f;
        #pragma unroll
        for (int j = 0; j < 16; j++) {
            float sc = s[j] * 0.125f;   // 1/sqrt(64)
            int kglob = kt * 64 + ql + j * 4;
            if (kglob > qglob) sc = -1e30f;
            s[j] = sc;
            mrow = fmaxf(mrow, sc);
        }
        mrow = fmaxf(mrow, __shfl_xor_sync(0xffffffffu, mrow, 1));
        mrow = fmaxf(mrow, __shfl_xor_sync(0xffffffffu, mrow, 2));
        float m_new = fmaxf(m_i, mrow);
        float fac = __expf(m_i - m_new);
        float lrow = 0.f;
        #pragma unroll
        for (int j = 0; j < 16; j++) {
            float p = __expf(s[j] - m_new);
            lrow += p;
            Ps[qr * AT_PAD + ql + j * 4] = p;
        }
        lrow += __shfl_xor_sync(0xffffffffu, lrow, 1);
        lrow += __shfl_xor_sync(0xffffffffu, lrow, 2);
        l_i = l_i * fac + lrow;
        m_i = m_new;
        #pragma unroll
        for (int j = 0; j < 16; j++) acc[j] *= fac;
        __syncthreads();

        // PV: thread owns dh in [ql*16, ql*16+16)
        int dbase = ql * 16;
        #pragma unroll
        for (int kc4 = 0; kc4 < 16; kc4++) {
            float4 p4 = *(const float4*)&Ps[qr * AT_PAD + kc4 * 4];
            float parr[4] = {p4.x, p4.y, p4.z, p4.w};
            #pragma unroll
            for (int kk = 0; kk < 4; kk++) {
                float pp = parr[kk];
                const float* vrow = &Vs[(kc4 * 4 + kk) * AT_PAD + dbase];
                float4 v0 = *(const float4*)(vrow);
                float4 v1 = *(const float4*)(vrow + 4);
                float4 v2 = *(const float4*)(vrow + 8);
                float4 v3 = *(const float4*)(vrow + 12);
                acc[0]  += pp * v0.x; acc[1]  += pp * v0.y; acc[2]  += pp * v0.z; acc[3]  += pp * v0.w;
                acc[4]  += pp * v1.x; acc[5]  += pp * v1.y; acc[6]  += pp * v1.z; acc[7]  += pp * v1.w;
                acc[8]  += pp * v2.x; acc[9]  += pp * v2.y; acc[10] += pp * v2.z; acc[11] += pp * v2.w;
                acc[12] += pp * v3.x; acc[13] += pp * v3.y; acc[14] += pp * v3.z; acc[15] += pp * v3.w;
            }
        }
    }

    float inv = 1.0f / l_i;
    float* Og = O + (size_t)(b * Sseq + qglob) * Dmod + h * DHd + ql * 16;
    #pragma unroll
    for (int jj = 0; jj < 4; jj++) {
        float4 o;
        o.x = acc[jj * 4 + 0] * inv;
        o.y = acc[jj * 4 + 1] * inv;
        o.z = acc[jj * 4 + 2] * inv;
        o.w = acc[jj * 4 + 3] * inv;
        *(float4*)(Og + jj * 4) = o;
    }
}

// ---------------- launch
extern "C" void kernel_launch(void* const* d_in, const int* in_sizes, int n_in,
                              void* d_out, int out_size)
{
    const float* x    = (const float*)d_in[0];
    const float* Wq   = (const float*)d_in[1];
    const float* Wk   = (const float*)d_in[2];
    const float* Wv   = (const float*)d_in[3];
    const float* Wo   = (const float*)d_in[4];
    const float* bo   = (const float*)d_in[5];
    const float* W1   = (const float*)d_in[6];
    const float* b1   = (const float*)d_in[7];
    const float* W2   = (const float*)d_in[8];
    const float* b2   = (const float*)d_in[9];
    const float* ln1s = (const float*)d_in[10];
    const float* ln1b = (const float*)d_in[11];
    const float* ln2s = (const float*)d_in[12];
    const float* ln2b = (const float*)d_in[13];
    float* out = (float*)d_out;

    float *ph, *pq, *pk, *pv, *pctx, *px1, *ph2, *pff;
    cudaGetSymbolAddress((void**)&ph,   g_h);
    cudaGetSymbolAddress((void**)&pq,   g_q);
    cudaGetSymbolAddress((void**)&pk,   g_k);
    cudaGetSymbolAddress((void**)&pv,   g_v);
    cudaGetSymbolAddress((void**)&pctx, g_ctx);
    cudaGetSymbolAddress((void**)&px1,  g_x1);
    cudaGetSymbolAddress((void**)&ph2,  g_h2);
    cudaGetSymbolAddress((void**)&pff,  g_ff);

    cudaFuncSetAttribute(attn_kernel, cudaFuncAttributeMaxDynamicSharedMemorySize, ATT_SMEM);

    // 1) LN1
    ln_kernel<<<NROWS, 256>>>(x, ln1s, ln1b, ph);

    // 2) Q,K,V projections (scatter to [B,H,S,DH])
    dim3 gq(Dmod / 128, NROWS / 128);
    gemm_kernel<1><<<gq, 256>>>(ph, Wq, nullptr, nullptr, pq, NROWS, Dmod, Dmod);
    gemm_kernel<1><<<gq, 256>>>(ph, Wk, nullptr, nullptr, pk, NROWS, Dmod, Dmod);
    gemm_kernel<1><<<gq, 256>>>(ph, Wv, nullptr, nullptr, pv, NROWS, Dmod, Dmod);

    // 3) causal flash attention -> ctx in [B,S,D]
    attn_kernel<<<dim3(Sseq / 64, Bsz * Hh), 256, ATT_SMEM>>>(pq, pk, pv, pctx);

    // 4) Wo projection + bias + residual(x) -> x1
    gemm_kernel<2><<<gq, 256>>>(pctx, Wo, bo, x, px1, NROWS, Dmod, Dmod);

    // 5) LN2
    ln_kernel<<<NROWS, 256>>>(px1, ln2s, ln2b, ph2);

    // 6) FF1 + bias + GELU
    gemm_kernel<3><<<dim3(DFFd / 128, NROWS / 128), 256>>>(ph2, W1, b1, nullptr, pff, NROWS, DFFd, Dmod);

    // 7) FF2 + bias + residual(x1) -> out
    gemm_kernel<4><<<gq, 256>>>(pff, W2, b2, px1, out, NROWS, Dmod, DFFd);
}